// round 16
// baseline (speedup 1.0000x reference)
#include <cuda_runtime.h>
#include <cuda_bf16.h>

#define N_NODES 50000
#define N_EDGES 800000
#define D_IN    128
#define HF      64
#define NB      196            // ceil(50000/256) for alloc
#define GNB     391            // ceil(50000/128) gemm blocks (128 nodes/block)
#define GST     (GNB * 128)
#define AGB     6250           // ceil(50000/8) for agg (8 warps/block, warp=node)
#define GEMM_SMEM (128 * 64 * 4 + 128 * 33 * 16)   // sW 32KB + sF 67.6KB

// Static scratch (allocation is forbidden)
__device__ float g_ft[N_NODES * HF];
__device__ int   g_count[N_NODES];     // zero-init; k_alloc re-zeroes each replay
__device__ int   g_off[N_NODES];
__device__ int   g_cnt[N_NODES];
__device__ int   g_cursor[N_NODES];
__device__ int   g_srcs[N_EDGES];
__device__ int   g_total;

// Packed fp32x2 FMA (Blackwell FFMA2, PTX-only)
#define FMA2(acc, a, b) \
    asm("fma.rn.f32x2 %0, %1, %2, %0;" : "+l"(acc) : "l"(a), "l"(b))

__device__ __forceinline__ unsigned long long fpack2(float x) {
    unsigned long long v; asm("mov.b64 %0, {%1,%1};" : "=l"(v) : "f"(x));
    return v;
}
__device__ __forceinline__ void funpack(unsigned long long v, float& a, float& b) {
    asm("mov.b64 {%0,%1}, %2;" : "=f"(a), "=f"(b) : "l"(v));
}

// ---------------------------------------------------------------------------
// K1: ft = feat @ W ([N,128]@[128,64]). LANE = NODE.
// 128 threads/block = 128 nodes. Per k-chunk: lane reads its own 16B of feat
// (conflict-free, padded rows); W read as warp-wide BROADCAST LDS.128 from
// natural [k][c] layout (column pairs contiguous -> packed f32x2 acc).
// Two 32-col passes keep regs ~70. smem 100KB -> 2 blocks/SM (8 warps).
// Fused dst histogram; resets g_total.
// ---------------------------------------------------------------------------
__global__ __launch_bounds__(128) void k_gemm(const float* __restrict__ feat,
                                              const float* __restrict__ W,
                                              const int* __restrict__ dst) {
    extern __shared__ float sm[];
    float*  sW  = sm;                              // [128][64] natural
    float4* sF4 = (float4*)(sm + 128 * 64);        // [128][33] float4 (pad)

    int tid  = threadIdx.x;
    int gtid = blockIdx.x * 128 + tid;
    if (gtid == 0) g_total = 0;
    for (int e = gtid; e < N_EDGES; e += GST)
        atomicAdd(&g_count[dst[e]], 1);

    for (int idx = tid; idx < 128 * 64; idx += 128)
        sW[idx] = W[idx];

    int node0 = blockIdx.x * 128;
    const float4* fv = (const float4*)feat;
    for (int idx = tid; idx < 128 * 32; idx += 128) {
        int r = idx >> 5, s = idx & 31;
        int n = node0 + r;
        sF4[r * 33 + s] = (n < N_NODES) ? fv[n * 32 + s]
                                        : make_float4(0.f, 0.f, 0.f, 0.f);
    }
    __syncthreads();

    int node = node0 + tid;
    const ulonglong2* wseg = (const ulonglong2*)sW;   // 16 units per k-row
    float4* ftv = (float4*)g_ft;

    #pragma unroll
    for (int half = 0; half < 2; half++) {            // cols [0,32) then [32,64)
        unsigned long long acc[16];
        #pragma unroll
        for (int p = 0; p < 16; p++) acc[p] = 0ull;

        for (int k = 0; k < 32; k++) {                // 32 chunks x 4 k = K=128
            float4 av = sF4[tid * 33 + k];            // own row, conflict-free
            unsigned long long s0 = fpack2(av.x), s1 = fpack2(av.y);
            unsigned long long s2 = fpack2(av.z), s3 = fpack2(av.w);
            int kb = k * 4 * 16 + half * 8;           // ull2 index of W[4k][half*32]
            #pragma unroll
            for (int i = 0; i < 8; i++) {             // 8 segs of 4 cols
                ulonglong2 w0 = wseg[kb + i];          // broadcast loads
                ulonglong2 w1 = wseg[kb + 16 + i];
                ulonglong2 w2 = wseg[kb + 32 + i];
                ulonglong2 w3 = wseg[kb + 48 + i];
                FMA2(acc[2*i],   s0, w0.x); FMA2(acc[2*i+1], s0, w0.y);
                FMA2(acc[2*i],   s1, w1.x); FMA2(acc[2*i+1], s1, w1.y);
                FMA2(acc[2*i],   s2, w2.x); FMA2(acc[2*i+1], s2, w2.y);
                FMA2(acc[2*i],   s3, w3.x); FMA2(acc[2*i+1], s3, w3.y);
            }
        }

        if (node < N_NODES) {
            #pragma unroll
            for (int v = 0; v < 4; v++) {
                float x, y, z, w;
                funpack(acc[4*v],     x, y);
                funpack(acc[4*v + 1], z, w);
                float4 o1 = make_float4(x, y, z, w);
                funpack(acc[4*v + 2], x, y);
                funpack(acc[4*v + 3], z, w);
                float4 o2 = make_float4(x, y, z, w);
                ftv[node * 16 + half * 8 + 2*v]     = o1;
                ftv[node * 16 + half * 8 + 2*v + 1] = o2;
            }
        }
    }
}

// ---------------------------------------------------------------------------
// K2: segment allocation via global atomic cursor; re-zero g_count for replay.
// ---------------------------------------------------------------------------
__global__ void k_alloc() {
    int i = blockIdx.x * 256 + threadIdx.x;
    if (i < N_NODES) {
        int cnt = g_count[i];
        g_count[i] = 0;
        int off = atomicAdd(&g_total, cnt);
        g_off[i]    = off;
        g_cnt[i]    = cnt;
        g_cursor[i] = off;
    }
}

// ---------------------------------------------------------------------------
// K3: place src ids into per-dst segments
// ---------------------------------------------------------------------------
__global__ void k_place(const int* __restrict__ src, const int* __restrict__ dst) {
    int e = blockIdx.x * 256 + threadIdx.x;            // exact: 3125*256
    int pos = atomicAdd(&g_cursor[dst[e]], 1);
    g_srcs[pos] = src[e];
}

// ---------------------------------------------------------------------------
// K4: fused score + softmax + aggregate. ONE WARP PER NODE. (R13 verbatim,
// measured 34.0us.) 32 lanes = 2 edges x 16 lanes; lane j owns float4 #j.
// 32-bit addressing; unpredicated full-pair path; odd edge peeled; x4 unroll.
// out[d] = (sum_e exp(e)*ft[src_e]) / sum_e exp(e)
// ---------------------------------------------------------------------------
__global__ __launch_bounds__(256) void k_agg(float* __restrict__ out) {
    const unsigned FULL = 0xffffffffu;
    int warp = (blockIdx.x * 256 + threadIdx.x) >> 5;  // node id
    if (warp >= N_NODES) return;
    int lane = threadIdx.x & 31;
    int j    = lane & 15;
    int e    = lane >> 4;

    const float4* __restrict__ ftv = (const float4*)g_ft;
    float4 b = ftv[warp * 16 + j];

    int beg = g_off[warp], cnt = g_cnt[warp];
    float4 acc = make_float4(0.f, 0.f, 0.f, 0.f);
    float den = 0.f;

#define EDGEF(A) do {                                                 \
        float p = (A).x * b.x + (A).y * b.y + (A).z * b.z + (A).w * b.w; \
        p += __shfl_xor_sync(FULL, p, 1);                             \
        p += __shfl_xor_sync(FULL, p, 2);                             \
        float ex = __expf(p * 0.25f);                                 \
        acc.x += ex * (A).x; acc.y += ex * (A).y;                     \
        acc.z += ex * (A).z; acc.w += ex * (A).w;                     \
        den += ex;                                                    \
    } while (0)

    for (int k0 = 0; k0 < cnt; k0 += 32) {
        int lim = cnt - k0; if (lim > 32) lim = 32;
        int myidx = (lane < lim) ? g_srcs[beg + k0 + lane] : 0;
        int npair = lim >> 1;

        int t = 0;
        for (; t + 4 <= npair; t += 4) {
            int s0 = __shfl_sync(FULL, myidx, 2 * t + e);
            int s1 = __shfl_sync(FULL, myidx, 2 * t + 2 + e);
            int s2 = __shfl_sync(FULL, myidx, 2 * t + 4 + e);
            int s3 = __shfl_sync(FULL, myidx, 2 * t + 6 + e);
            float4 a0 = ftv[s0 * 16 + j];
            float4 a1 = ftv[s1 * 16 + j];
            float4 a2 = ftv[s2 * 16 + j];
            float4 a3 = ftv[s3 * 16 + j];
            EDGEF(a0); EDGEF(a1); EDGEF(a2); EDGEF(a3);
        }
        for (; t < npair; ++t) {
            int s0 = __shfl_sync(FULL, myidx, 2 * t + e);
            float4 a0 = ftv[s0 * 16 + j];
            EDGEF(a0);
        }
        if (lim & 1) {
            int s0 = __shfl_sync(FULL, myidx, lim - 1);
            float4 a0 = ftv[s0 * 16 + j];
            float p = a0.x * b.x + a0.y * b.y + a0.z * b.z + a0.w * b.w;
            p += __shfl_xor_sync(FULL, p, 1);
            p += __shfl_xor_sync(FULL, p, 2);
            float ex = (e == 0) ? __expf(p * 0.25f) : 0.f;
            acc.x += ex * a0.x; acc.y += ex * a0.y;
            acc.z += ex * a0.z; acc.w += ex * a0.w;
            den += ex;
        }
    }
#undef EDGEF

    acc.x += __shfl_xor_sync(FULL, acc.x, 16);
    acc.y += __shfl_xor_sync(FULL, acc.y, 16);
    acc.z += __shfl_xor_sync(FULL, acc.z, 16);
    acc.w += __shfl_xor_sync(FULL, acc.w, 16);
    den   += __shfl_xor_sync(FULL, den,   16);

    if (lane < 16) {
        float inv = (den > 0.f) ? (1.f / den) : 0.f;
        ((float4*)out)[warp * 16 + j] =
            make_float4(acc.x * inv, acc.y * inv, acc.z * inv, acc.w * inv);
    }
}

// ---------------------------------------------------------------------------
extern "C" void kernel_launch(void* const* d_in, const int* in_sizes, int n_in,
                              void* d_out, int out_size) {
    const float* feat = (const float*)d_in[0];
    const float* W    = (const float*)d_in[1];
    const int*   src  = (const int*)d_in[2];
    const int*   dst  = (const int*)d_in[3];
    float* out = (float*)d_out;

    cudaFuncSetAttribute(k_gemm, cudaFuncAttributeMaxDynamicSharedMemorySize,
                         GEMM_SMEM);
    k_gemm <<<GNB, 128, GEMM_SMEM>>>(feat, W, dst);
    k_alloc<<<NB, 256>>>();
    k_place<<<N_EDGES / 256, 256>>>(src, dst);
    k_agg  <<<AGB, 256>>>(out);
}